// round 1
// baseline (speedup 1.0000x reference)
#include <cuda_runtime.h>

// CutStripes: out[b,0,t,f] = mask(b,t) ? x[perm[b],0,t,f] : x[b,0,t,f]
// mask(b,t) = any_s( bgn[b,s] <= t < bgn[b,s]+distance[b,s] )
// B=128, C=1, T=2048, F=128 (fp32). Pure HBM-bound copy with per-row select.

#define B_ 128
#define T_ 2048
#define F_ 128
#define STRIPES 4

// One float4 (16B) per thread; 32 threads (one warp) cover one (b,t) row of F=128 floats.
__global__ void __launch_bounds__(256)
cutstripes_kernel(const float4* __restrict__ x4,
                  const int*    __restrict__ perm,
                  const int*    __restrict__ bgn,
                  const int*    __restrict__ dist,
                  float4*       __restrict__ out4)
{
    int i    = blockIdx.x * blockDim.x + threadIdx.x;   // [0, B_*T_*32)
    int lane = i & 31;                                  // float4 index within row
    int row  = i >> 5;                                  // b*T + t
    int t    = row & (T_ - 1);                          // T_ = 2048 (pow2)
    int b    = row >> 11;

    // Per-(b,t) stripe mask: 4 compares; operand loads are warp-uniform -> broadcast.
    bool m = false;
#pragma unroll
    for (int s = 0; s < STRIPES; s++) {
        int lo = __ldg(&bgn[b * STRIPES + s]);
        int d  = __ldg(&dist[b * STRIPES + s]);
        m = m || (t >= lo && t < lo + d);
    }

    int src = m ? __ldg(&perm[b]) : b;

    // x4 index: ((src*T + t) * F + lane*4) / 4 = (src*T + t)*32 + lane
    out4[i] = x4[(((src << 11) | t) << 5) + lane];
}

extern "C" void kernel_launch(void* const* d_in, const int* in_sizes, int n_in,
                              void* d_out, int out_size)
{
    const float4* x4   = (const float4*)d_in[0];
    const int*    perm = (const int*)d_in[1];
    const int*    bgn  = (const int*)d_in[2];
    const int*    dist = (const int*)d_in[3];
    float4*       out4 = (float4*)d_out;

    const int total = B_ * T_ * (F_ / 4);   // 8,388,608 threads
    const int threads = 256;
    const int blocks  = total / threads;    // 32768

    cutstripes_kernel<<<blocks, threads>>>(x4, perm, bgn, dist, out4);
}

// round 2
// speedup vs baseline: 1.1007x; 1.1007x over previous
#include <cuda_runtime.h>

// CutStripes: out[b,0,t,f] = mask(b,t) ? x[perm[b],0,t,f] : x[b,0,t,f]
// B=128, C=1, T=2048, F=128 (fp32). HBM-bound row-select copy.
// R2: ILP=4 (4 independent LDG.128 per thread, batched) + streaming stores.

#define B_ 128
#define T_ 2048
#define F_ 128
#define STRIPES 4
#define ILP 4

// One warp covers one (b,t) row per load step; each thread owns lane `lane`
// of ILP consecutive t-rows (all within the same b since ILP | 2048).
__global__ void __launch_bounds__(256)
cutstripes_kernel(const float4* __restrict__ x4,
                  const int*    __restrict__ perm,
                  const int*    __restrict__ bgn,
                  const int*    __restrict__ dist,
                  float4*       __restrict__ out4)
{
    int i       = blockIdx.x * blockDim.x + threadIdx.x;  // [0, B_*T_*32/ILP)
    int lane    = i & 31;                                 // float4 index within row
    int rowBase = (i >> 5) * ILP;                         // b*T + t0
    int t0      = rowBase & (T_ - 1);
    int b       = rowBase >> 11;

    // Stripe params for this b (warp-uniform broadcast loads).
    int lo0 = __ldg(&bgn[b * STRIPES + 0]), d0 = __ldg(&dist[b * STRIPES + 0]);
    int lo1 = __ldg(&bgn[b * STRIPES + 1]), d1 = __ldg(&dist[b * STRIPES + 1]);
    int lo2 = __ldg(&bgn[b * STRIPES + 2]), d2 = __ldg(&dist[b * STRIPES + 2]);
    int lo3 = __ldg(&bgn[b * STRIPES + 3]), d3 = __ldg(&dist[b * STRIPES + 3]);
    int p   = __ldg(&perm[b]);

    float4 v[ILP];
#pragma unroll
    for (int k = 0; k < ILP; k++) {
        int t = t0 + k;
        bool m = (t >= lo0 && t < lo0 + d0) |
                 (t >= lo1 && t < lo1 + d1) |
                 (t >= lo2 && t < lo2 + d2) |
                 (t >= lo3 && t < lo3 + d3);
        int src = m ? p : b;
        v[k] = x4[(((src << 11) | t) << 5) + lane];   // (src*T + t)*32 + lane
    }

#pragma unroll
    for (int k = 0; k < ILP; k++) {
        // Output row = rowBase + k; never re-read -> streaming store.
        __stcs(&out4[((rowBase + k) << 5) + lane], v[k]);
    }
}

extern "C" void kernel_launch(void* const* d_in, const int* in_sizes, int n_in,
                              void* d_out, int out_size)
{
    const float4* x4   = (const float4*)d_in[0];
    const int*    perm = (const int*)d_in[1];
    const int*    bgn  = (const int*)d_in[2];
    const int*    dist = (const int*)d_in[3];
    float4*       out4 = (float4*)d_out;

    const int total   = B_ * T_ * (F_ / 4) / ILP;  // 2,097,152 threads
    const int threads = 256;
    const int blocks  = total / threads;           // 8192

    cutstripes_kernel<<<blocks, threads>>>(x4, perm, bgn, dist, out4);
}